// round 1
// baseline (speedup 1.0000x reference)
#include <cuda_runtime.h>
#include <cuda_bf16.h>
#include <math_constants.h>

// Problem constants
#define B_   1024
#define NTOK 68
#define C_   768
#define H_   12
#define HD   64
#define M_   (B_ * NTOK)        // 69632
#define K3C  (3 * C_)           // 2304

// Scratch (allocation-free rule: __device__ globals)
__device__ float g_qkv[(size_t)M_ * K3C];   // (B*N, 3C): [which][head][hd] in cols
__device__ float g_att[(size_t)M_ * C_];    // attention output in (B, N, H*hd)

// ---------------------------------------------------------------------------
// Tiled SGEMM: Cmn = sum_k A[m][k] * W[n][k] + bias[n]
// A: M x K row-major, W: N x K row-major, C: M x N row-major.
// ADD_PE: A[m][k] += pe[(m%68)+28][k] when (m%68) >= 4  (fused PE add)
// BM=BN=128, BK=8, TM=TN=8, 256 threads. All dims assumed divisible.
// ---------------------------------------------------------------------------
template <bool ADD_PE>
__global__ __launch_bounds__(256)
void sgemm_bias_kernel(const float* __restrict__ A,
                       const float* __restrict__ W,
                       const float* __restrict__ bias,
                       const float* __restrict__ pe,
                       float* __restrict__ C,
                       int M, int N, int K)
{
    constexpr int BM = 128, BN = 128, BK = 8, TM = 8, TN = 8;
    __shared__ float As[BK][BM];
    __shared__ float Bs[BK][BN];

    const int tid  = threadIdx.x;          // 0..255
    const int cRow = blockIdx.y;
    const int cCol = blockIdx.x;

    const int tRow = tid / 16;              // 0..15
    const int tCol = tid % 16;              // 0..15

    // each thread loads one float4 of A-tile and one of W-tile per k-step
    const int ldRow = tid >> 1;             // 0..127
    const int ldCol = (tid & 1) * 4;        // 0 or 4

    const float* Aptr = A + (size_t)cRow * BM * K;
    const float* Wptr = W + (size_t)cCol * BN * K;

    float acc[TM][TN];
#pragma unroll
    for (int i = 0; i < TM; i++)
#pragma unroll
        for (int j = 0; j < TN; j++) acc[i][j] = 0.0f;

    for (int k0 = 0; k0 < K; k0 += BK) {
        // --- load A tile (with optional fused PE add) ---
        float4 a4 = *reinterpret_cast<const float4*>(Aptr + (size_t)ldRow * K + k0 + ldCol);
        if (ADD_PE) {
            int m = cRow * BM + ldRow;
            int n = m % NTOK;
            if (n >= 4) {
                const float4 p4 = *reinterpret_cast<const float4*>(
                    pe + (size_t)(n + 28) * K + k0 + ldCol);
                a4.x += p4.x; a4.y += p4.y; a4.z += p4.z; a4.w += p4.w;
            }
        }
        As[ldCol + 0][ldRow] = a4.x;
        As[ldCol + 1][ldRow] = a4.y;
        As[ldCol + 2][ldRow] = a4.z;
        As[ldCol + 3][ldRow] = a4.w;

        // --- load W tile (same pattern; W is N x K row-major) ---
        const float4 b4 = *reinterpret_cast<const float4*>(Wptr + (size_t)ldRow * K + k0 + ldCol);
        Bs[ldCol + 0][ldRow] = b4.x;
        Bs[ldCol + 1][ldRow] = b4.y;
        Bs[ldCol + 2][ldRow] = b4.z;
        Bs[ldCol + 3][ldRow] = b4.w;

        __syncthreads();

#pragma unroll
        for (int k = 0; k < BK; k++) {
            float rm[TM], rn[TN];
            const float4 m0 = *reinterpret_cast<const float4*>(&As[k][tRow * TM]);
            const float4 m1 = *reinterpret_cast<const float4*>(&As[k][tRow * TM + 4]);
            rm[0]=m0.x; rm[1]=m0.y; rm[2]=m0.z; rm[3]=m0.w;
            rm[4]=m1.x; rm[5]=m1.y; rm[6]=m1.z; rm[7]=m1.w;
            const float4 n0 = *reinterpret_cast<const float4*>(&Bs[k][tCol * TN]);
            const float4 n1 = *reinterpret_cast<const float4*>(&Bs[k][tCol * TN + 4]);
            rn[0]=n0.x; rn[1]=n0.y; rn[2]=n0.z; rn[3]=n0.w;
            rn[4]=n1.x; rn[5]=n1.y; rn[6]=n1.z; rn[7]=n1.w;
#pragma unroll
            for (int i = 0; i < TM; i++)
#pragma unroll
                for (int j = 0; j < TN; j++)
                    acc[i][j] = fmaf(rm[i], rn[j], acc[i][j]);
        }
        __syncthreads();
    }

    // --- epilogue: add bias, vectorized store ---
#pragma unroll
    for (int i = 0; i < TM; i++) {
        const int row = cRow * BM + tRow * TM + i;
#pragma unroll
        for (int j = 0; j < TN; j += 4) {
            const int col = cCol * BN + tCol * TN + j;
            float4 o;
            o.x = acc[i][j + 0] + bias[col + 0];
            o.y = acc[i][j + 1] + bias[col + 1];
            o.z = acc[i][j + 2] + bias[col + 2];
            o.w = acc[i][j + 3] + bias[col + 3];
            *reinterpret_cast<float4*>(C + (size_t)row * N + col) = o;
        }
    }
}

// ---------------------------------------------------------------------------
// Attention: one CTA per (b, h). N=68 keys, hd=64.
// Reads q/k/v slices from g_qkv, softmax(q k^T * scale + mask) @ v,
// writes g_att in (B, N, H*hd) layout.
// ---------------------------------------------------------------------------
__global__ __launch_bounds__(256)
void attention_kernel(const float* __restrict__ qkv,
                      const float* __restrict__ mask,
                      float* __restrict__ out)
{
    __shared__ float sk[NTOK][HD + 1];   // padded: stride 65 -> conflict-free
    __shared__ float sv[NTOK][HD + 1];
    __shared__ float sq[8][HD];
    __shared__ float sp[8][NTOK];

    const int bh = blockIdx.x;
    const int b  = bh / H_;
    const int h  = bh % H_;
    const int tid  = threadIdx.x;
    const int warp = tid >> 5;
    const int lane = tid & 31;

    const size_t base = (size_t)b * NTOK * K3C + (size_t)h * HD;
    // stage K and V tiles
    for (int idx = tid; idx < NTOK * HD; idx += 256) {
        const int j = idx / HD, d = idx % HD;
        sk[j][d] = qkv[base + (size_t)j * K3C + C_ + d];
        sv[j][d] = qkv[base + (size_t)j * K3C + 2 * C_ + d];
    }
    __syncthreads();

    const float scale = 0.125f;   // 64^-0.5
    const float* mrow_base = mask + (size_t)b * NTOK * NTOK;

    for (int i = warp; i < NTOK; i += 8) {
        // load q row (scaled) into per-warp smem
        sq[warp][lane]      = qkv[base + (size_t)i * K3C + lane]      * scale;
        sq[warp][lane + 32] = qkv[base + (size_t)i * K3C + lane + 32] * scale;
        __syncwarp();

        // scores for keys j = lane, lane+32, lane+64
        float s[3];
#pragma unroll
        for (int t = 0; t < 3; t++) {
            const int j = lane + 32 * t;
            if (j < NTOK) {
                float acc = 0.0f;
#pragma unroll
                for (int d = 0; d < HD; d++)
                    acc = fmaf(sq[warp][d], sk[j][d], acc);
                s[t] = acc + mrow_base[(size_t)i * NTOK + j];
            } else {
                s[t] = -CUDART_INF_F;
            }
        }

        // softmax over 68 values spread across the warp
        float mx = fmaxf(fmaxf(s[0], s[1]), s[2]);
#pragma unroll
        for (int off = 16; off > 0; off >>= 1)
            mx = fmaxf(mx, __shfl_xor_sync(0xffffffffu, mx, off));

        float e[3], sum = 0.0f;
#pragma unroll
        for (int t = 0; t < 3; t++) {
            e[t] = (lane + 32 * t < NTOK) ? __expf(s[t] - mx) : 0.0f;
            sum += e[t];
        }
#pragma unroll
        for (int off = 16; off > 0; off >>= 1)
            sum += __shfl_xor_sync(0xffffffffu, sum, off);
        const float inv = 1.0f / sum;

#pragma unroll
        for (int t = 0; t < 3; t++) {
            const int j = lane + 32 * t;
            if (j < NTOK) sp[warp][j] = e[t] * inv;
        }
        __syncwarp();

        // out[d] = sum_j p[j] * v[j][d], lanes own d and d+32
        float o0 = 0.0f, o1 = 0.0f;
#pragma unroll
        for (int j = 0; j < NTOK; j++) {
            const float p = sp[warp][j];
            o0 = fmaf(p, sv[j][lane],      o0);
            o1 = fmaf(p, sv[j][lane + 32], o1);
        }
        float* orow = out + ((size_t)b * NTOK + i) * C_ + (size_t)h * HD;
        orow[lane]      = o0;
        orow[lane + 32] = o1;
        __syncwarp();
    }
}

// ---------------------------------------------------------------------------
extern "C" void kernel_launch(void* const* d_in, const int* in_sizes, int n_in,
                              void* d_out, int out_size)
{
    const float* x      = (const float*)d_in[0];
    const float* pe     = (const float*)d_in[1];
    const float* mask   = (const float*)d_in[2];
    const float* w_qkv  = (const float*)d_in[3];
    const float* b_qkv  = (const float*)d_in[4];
    const float* w_proj = (const float*)d_in[5];
    const float* b_proj = (const float*)d_in[6];
    float* out = (float*)d_out;

    float* qkv_buf;  cudaGetSymbolAddress((void**)&qkv_buf, g_qkv);
    float* att_buf;  cudaGetSymbolAddress((void**)&att_buf, g_att);

    // 1) QKV projection with fused PE add: (M x 768) @ (768 x 2304)^T + bias
    {
        dim3 grid(K3C / 128, M_ / 128);
        sgemm_bias_kernel<true><<<grid, 256>>>(x, w_qkv, b_qkv, pe, qkv_buf,
                                               M_, K3C, C_);
    }

    // 2) Attention per (b, h)
    attention_kernel<<<B_ * H_, 256>>>(qkv_buf, mask, att_buf);

    // 3) Output projection: (M x 768) @ (768 x 768)^T + bias -> d_out
    {
        dim3 grid(C_ / 128, M_ / 128);
        sgemm_bias_kernel<false><<<grid, 256>>>(att_buf, w_proj, b_proj, nullptr,
                                                out, M_, C_, C_);
    }
}

// round 3
// speedup vs baseline: 2.1598x; 2.1598x over previous
#include <cuda_runtime.h>
#include <cuda_bf16.h>
#include <math_constants.h>
#include <cstdint>

// Problem constants
#define B_   1024
#define NTOK 68
#define C_   768
#define H_   12
#define HD   64
#define M_   (B_ * NTOK)        // 69632
#define K3C  (3 * C_)           // 2304

// Scratch (__device__ globals; allocation-free rule)
__device__ float         g_qkv[(size_t)M_ * K3C];   // QKV output fp32
__device__ __nv_bfloat16 g_xhi[(size_t)M_ * C_];    // x+pe split
__device__ __nv_bfloat16 g_xlo[(size_t)M_ * C_];
__device__ __nv_bfloat16 g_whi[(size_t)K3C * C_];   // w_qkv split
__device__ __nv_bfloat16 g_wlo[(size_t)K3C * C_];
__device__ __nv_bfloat16 g_phi[(size_t)C_ * C_];    // w_proj split
__device__ __nv_bfloat16 g_plo[(size_t)C_ * C_];
__device__ __nv_bfloat16 g_ahi[(size_t)M_ * C_];    // attention out split
__device__ __nv_bfloat16 g_alo[(size_t)M_ * C_];

// ---------------------------------------------------------------------------
// helpers
// ---------------------------------------------------------------------------
static __device__ __forceinline__ uint32_t smem_u32(const void* p) {
    uint32_t a;
    asm("{ .reg .u64 t; cvta.to.shared.u64 t, %1; cvt.u32.u64 %0, t; }"
        : "=r"(a) : "l"(p));
    return a;
}

static __device__ __forceinline__ void split2(float v, __nv_bfloat16& h,
                                              __nv_bfloat16& l) {
    h = __float2bfloat16_rn(v);
    l = __float2bfloat16_rn(v - __bfloat162float(h));
}

#define CP16(dst, src) \
    asm volatile("cp.async.cg.shared.global [%0], [%1], 16;" \
                 :: "r"(dst), "l"(src))
#define CP_COMMIT() asm volatile("cp.async.commit_group;" ::: "memory")
#define CP_WAIT1()  asm volatile("cp.async.wait_group 1;"  ::: "memory")

#define LDSM_X4(r, addr) \
    asm volatile("ldmatrix.sync.aligned.m8n8.x4.shared.b16 {%0,%1,%2,%3}, [%4];" \
                 : "=r"((r)[0]), "=r"((r)[1]), "=r"((r)[2]), "=r"((r)[3]) \
                 : "r"(addr))

#define MMA_BF16(d, a, b0, b1) \
    asm volatile("mma.sync.aligned.m16n8k16.row.col.f32.bf16.bf16.f32 " \
                 "{%0,%1,%2,%3}, {%4,%5,%6,%7}, {%8,%9}, {%0,%1,%2,%3};" \
                 : "+f"((d)[0]), "+f"((d)[1]), "+f"((d)[2]), "+f"((d)[3]) \
                 : "r"((a)[0]), "r"((a)[1]), "r"((a)[2]), "r"((a)[3]), \
                   "r"(b0), "r"(b1))

// smem tile layout: 128 rows x 64 bytes (32 bf16), XOR swizzle for conflict-
// free ldmatrix. 2 stages x 4 tiles (Ahi, Alo, Bhi, Blo) x 8KB = 64KB.
static __device__ __forceinline__ uint32_t sw_off(int row, int c) {
    const int s = (row & 3) ^ ((row >> 2) & 3);
    return (uint32_t)(row * 64 + ((c ^ s) << 4));
}
#define TILE_ST(s, w) ((s) * 32768 + (w) * 8192)
#define GEMM_SMEM 65536

// ---------------------------------------------------------------------------
// split kernels (fp32 -> bf16 hi/lo pair)
// ---------------------------------------------------------------------------
__global__ void split_x_pe_kernel(const float* __restrict__ x,
                                  const float* __restrict__ pe,
                                  __nv_bfloat16* __restrict__ hi,
                                  __nv_bfloat16* __restrict__ lo)
{
    const size_t i4 = (size_t)blockIdx.x * blockDim.x + threadIdx.x;
    const size_t e  = i4 * 4;
    if (e >= (size_t)M_ * C_) return;
    const int row = (int)(e / C_);
    const int col = (int)(e % C_);
    const int tok = row % NTOK;

    float4 v = *reinterpret_cast<const float4*>(x + e);
    if (tok >= 4) {
        const float4 p = *reinterpret_cast<const float4*>(
            pe + (size_t)(tok + 28) * C_ + col);
        v.x += p.x; v.y += p.y; v.z += p.z; v.w += p.w;
    }
    __nv_bfloat16 h0, l0, h1, l1, h2, l2, h3, l3;
    split2(v.x, h0, l0); split2(v.y, h1, l1);
    split2(v.z, h2, l2); split2(v.w, h3, l3);
    __nv_bfloat162* hp = reinterpret_cast<__nv_bfloat162*>(hi + e);
    __nv_bfloat162* lp = reinterpret_cast<__nv_bfloat162*>(lo + e);
    hp[0] = __nv_bfloat162(h0, h1); hp[1] = __nv_bfloat162(h2, h3);
    lp[0] = __nv_bfloat162(l0, l1); lp[1] = __nv_bfloat162(l2, l3);
}

__global__ void split_w_kernel(const float* __restrict__ w,
                               __nv_bfloat16* __restrict__ hi,
                               __nv_bfloat16* __restrict__ lo,
                               size_t n_elem)
{
    const size_t i4 = (size_t)blockIdx.x * blockDim.x + threadIdx.x;
    const size_t e  = i4 * 4;
    if (e >= n_elem) return;
    const float4 v = *reinterpret_cast<const float4*>(w + e);
    __nv_bfloat16 h0, l0, h1, l1, h2, l2, h3, l3;
    split2(v.x, h0, l0); split2(v.y, h1, l1);
    split2(v.z, h2, l2); split2(v.w, h3, l3);
    __nv_bfloat162* hp = reinterpret_cast<__nv_bfloat162*>(hi + e);
    __nv_bfloat162* lp = reinterpret_cast<__nv_bfloat162*>(lo + e);
    hp[0] = __nv_bfloat162(h0, h1); hp[1] = __nv_bfloat162(h2, h3);
    lp[0] = __nv_bfloat162(l0, l1); lp[1] = __nv_bfloat162(l2, l3);
}

// ---------------------------------------------------------------------------
// GEMM: C[m][n] = sum_k (Ahi+Alo)[m][k] * (Bhi+Blo)[n][k] + bias[n]
// using D = Ahi*Bhi + Ahi*Blo + Alo*Bhi  (bf16 mma.sync, fp32 accum)
// A: M x K row-major bf16 pair, B: N x K row-major bf16 pair. K % 32 == 0.
// CTA 128x128, 8 warps in 2(m) x 4(n), warp tile 64x32.
// ---------------------------------------------------------------------------
__global__ __launch_bounds__(256)
void gemm_bf16x3_kernel(const __nv_bfloat16* __restrict__ Ahi,
                        const __nv_bfloat16* __restrict__ Alo,
                        const __nv_bfloat16* __restrict__ Bhi,
                        const __nv_bfloat16* __restrict__ Blo,
                        const float* __restrict__ bias,
                        float* __restrict__ Cout,
                        int N, int K)
{
    extern __shared__ char smem[];
    const uint32_t sb = smem_u32(smem);

    const int tid  = threadIdx.x;
    const int wid  = tid >> 5;
    const int lane = tid & 31;
    const int cN   = blockIdx.x;
    const int cM   = blockIdx.y;
    const int wm   = wid & 1;    // 0..1
    const int wn   = wid >> 1;   // 0..3

    // ---- load geometry: 2 x 16B chunks per thread per tile ----
    const int id0 = tid,        r0 = id0 >> 2, c0 = id0 & 3;
    const int id1 = tid + 256,  r1 = id1 >> 2, c1 = id1 & 3;
    const uint32_t so0 = sw_off(r0, c0);
    const uint32_t so1 = sw_off(r1, c1);
    const __nv_bfloat16* gAh0 = Ahi + (size_t)(cM * 128 + r0) * K + c0 * 8;
    const __nv_bfloat16* gAh1 = Ahi + (size_t)(cM * 128 + r1) * K + c1 * 8;
    const __nv_bfloat16* gAl0 = Alo + (size_t)(cM * 128 + r0) * K + c0 * 8;
    const __nv_bfloat16* gAl1 = Alo + (size_t)(cM * 128 + r1) * K + c1 * 8;
    const __nv_bfloat16* gBh0 = Bhi + (size_t)(cN * 128 + r0) * K + c0 * 8;
    const __nv_bfloat16* gBh1 = Bhi + (size_t)(cN * 128 + r1) * K + c1 * 8;
    const __nv_bfloat16* gBl0 = Blo + (size_t)(cN * 128 + r0) * K + c0 * 8;
    const __nv_bfloat16* gBl1 = Blo + (size_t)(cN * 128 + r1) * K + c1 * 8;

#define LOAD_STAGE(s, k0)                                            \
    do {                                                              \
        CP16(sb + TILE_ST(s, 0) + so0, gAh0 + (k0));                  \
        CP16(sb + TILE_ST(s, 0) + so1, gAh1 + (k0));                  \
        CP16(sb + TILE_ST(s, 1) + so0, gAl0 + (k0));                  \
        CP16(sb + TILE_ST(s, 1) + so1, gAl1 + (k0));                  \
        CP16(sb + TILE_ST(s, 2) + so0, gBh0 + (k0));                  \
        CP16(sb + TILE_ST(s, 2) + so1, gBh1 + (k0));                  \
        CP16(sb + TILE_ST(s, 3) + so0, gBl0 + (k0));                  \
        CP16(sb + TILE_ST(s, 3) + so1, gBl1 + (k0));                  \
    } while (0)

    float acc[4][4][4];
#pragma unroll
    for (int i = 0; i < 4; i++)
#pragma unroll
        for (int j = 0; j < 4; j++)
#pragma unroll
            for (int r = 0; r < 4; r++) acc[i][j][r] = 0.0f;

    const int NC = K >> 5;   // chunks of 32

    LOAD_STAGE(0, 0);
    CP_COMMIT();
    LOAD_STAGE(1, 32);
    CP_COMMIT();

    // per-warp ldmatrix base offsets
    const int arow = wm * 64 + (lane & 15);       // + mf*16
    const int brow = wn * 32 + (lane & 15);       // + bf*16
    const int chi  = lane >> 4;                   // 0/1 -> k-lo/k-hi 16B chunk

    for (int kc = 0; kc < NC; kc++) {
        const int cur = kc & 1;
        CP_WAIT1();
        __syncthreads();

        uint32_t Ah[2][4][4], Al[2][4][4], Bh[2][2][4], Bl[2][2][4];

        // ---- t = 0 fragments ----
#pragma unroll
        for (int mf = 0; mf < 4; mf++) {
            const uint32_t ao = sw_off(arow + mf * 16, chi);
            LDSM_X4(Ah[0][mf], sb + TILE_ST(cur, 0) + ao);
            LDSM_X4(Al[0][mf], sb + TILE_ST(cur, 1) + ao);
        }
#pragma unroll
        for (int bf = 0; bf < 2; bf++) {
            const uint32_t bo = sw_off(brow + bf * 16, chi);
            LDSM_X4(Bh[0][bf], sb + TILE_ST(cur, 2) + bo);
            LDSM_X4(Bl[0][bf], sb + TILE_ST(cur, 3) + bo);
        }
        // ---- t = 1 fragments ----
#pragma unroll
        for (int mf = 0; mf < 4; mf++) {
            const uint32_t ao = sw_off(arow + mf * 16, 2 + chi);
            LDSM_X4(Ah[1][mf], sb + TILE_ST(cur, 0) + ao);
            LDSM_X4(Al[1][mf], sb + TILE_ST(cur, 1) + ao);
        }
#pragma unroll
        for (int bf = 0; bf < 2; bf++) {
            const uint32_t bo = sw_off(brow + bf * 16, 2 + chi);
            LDSM_X4(Bh[1][bf], sb + TILE_ST(cur, 2) + bo);
            LDSM_X4(Bl[1][bf], sb + TILE_ST(cur, 3) + bo);
        }

        __syncthreads();   // all warps done reading stage `cur`
        if (kc + 2 < NC) LOAD_STAGE(cur, (kc + 2) * 32);
        CP_COMMIT();

        // ---- MMAs (overlap with cp.async in flight) ----
#pragma unroll
        for (int t = 0; t < 2; t++) {
#pragma unroll
            for (int mf = 0; mf < 4; mf++) {
#pragma unroll
                for (int nf = 0; nf < 4; nf++) {
                    const int g = nf >> 1, h = nf & 1;
                    const uint32_t bh0 = Bh[t][g][h], bh1 = Bh[t][g][h + 2];
                    const uint32_t bl0 = Bl[t][g][h], bl1 = Bl[t][g][h + 2];
                    MMA_BF16(acc[mf][nf], Ah[t][mf], bh0, bh1);
                    MMA_BF16(acc[mf][nf], Ah[t][mf], bl0, bl1);
                    MMA_BF16(acc[mf][nf], Al[t][mf], bh0, bh1);
                }
            }
        }
    }

    // ---- epilogue: bias + store fp32 ----
#pragma unroll
    for (int mf = 0; mf < 4; mf++) {
        const int row = cM * 128 + wm * 64 + mf * 16 + (lane >> 2);
#pragma unroll
        for (int nf = 0; nf < 4; nf++) {
            const int col = cN * 128 + wn * 32 + nf * 8 + (lane & 3) * 2;
            const float2 bb = *reinterpret_cast<const float2*>(bias + col);
            float2 o0, o1;
            o0.x = acc[mf][nf][0] + bb.x;  o0.y = acc[mf][nf][1] + bb.y;
            o1.x = acc[mf][nf][2] + bb.x;  o1.y = acc[mf][nf][3] + bb.y;
            *reinterpret_cast<float2*>(Cout + (size_t)row * N + col) = o0;
            *reinterpret_cast<float2*>(Cout + (size_t)(row + 8) * N + col) = o1;
        }
    }
#undef LOAD_STAGE
}

// ---------------------------------------------------------------------------
// Attention: one CTA per (b, h). Writes bf16 hi/lo split of output directly.
// ---------------------------------------------------------------------------
__global__ __launch_bounds__(256)
void attention_kernel(const float* __restrict__ qkv,
                      const float* __restrict__ mask,
                      __nv_bfloat16* __restrict__ ohi,
                      __nv_bfloat16* __restrict__ olo)
{
    __shared__ float sk[NTOK][HD + 1];
    __shared__ float sv[NTOK][HD + 1];
    __shared__ float sq[8][HD];
    __shared__ float sp[8][NTOK];

    const int bh = blockIdx.x;
    const int b  = bh / H_;
    const int h  = bh % H_;
    const int tid  = threadIdx.x;
    const int warp = tid >> 5;
    const int lane = tid & 31;

    const size_t base = (size_t)b * NTOK * K3C + (size_t)h * HD;
    for (int idx = tid; idx < NTOK * HD; idx += 256) {
        const int j = idx / HD, d = idx % HD;
        sk[j][d] = qkv[base + (size_t)j * K3C + C_ + d];
        sv[j][d] = qkv[base + (size_t)j * K3C + 2 * C_ + d];
    }
    __syncthreads();

    const float scale = 0.125f;
    const float* mrow_base = mask + (size_t)b * NTOK * NTOK;

    for (int i = warp; i < NTOK; i += 8) {
        sq[warp][lane]      = qkv[base + (size_t)i * K3C + lane]      * scale;
        sq[warp][lane + 32] = qkv[base + (size_t)i * K3C + lane + 32] * scale;
        __syncwarp();

        float s[3];
#pragma unroll
        for (int t = 0; t < 3; t++) {
            const int j = lane + 32 * t;
            if (j < NTOK) {
                float a = 0.0f;
#pragma unroll
                for (int d = 0; d < HD; d++)
                    a = fmaf(sq[warp][d], sk[j][d], a);
                s[t] = a + mrow_base[(size_t)i * NTOK + j];
            } else {
                s[t] = -CUDART_INF_F;
            }
        }

        float mx = fmaxf(fmaxf(s[0], s[1]), s[2]);
#pragma unroll
        for (int off = 16; off > 0; off >>= 1)
            mx = fmaxf(mx, __shfl_xor_sync(0xffffffffu, mx, off));

        float e[3], sum = 0.0f;
#pragma unroll
        for (int t = 0; t < 3; t++) {
            e[t] = (lane + 32 * t < NTOK) ? __expf(s[t] - mx) : 0.0f;
            sum += e[t];
        }
#pragma unroll
        for (int off = 16; off > 0; off >>= 1)
            sum += __shfl_xor_sync(0xffffffffu, sum, off);
        const float inv = 1.0f / sum;

#pragma unroll
        for (int t = 0; t < 3; t++) {
            const int j = lane + 32 * t;
            if (j < NTOK) sp[warp][j] = e[t] * inv;
        }
        __syncwarp();

        float o0 = 0.0f, o1 = 0.0f;
#pragma unroll
        for (int j = 0; j < NTOK; j++) {
            const float p = sp[warp][j];
            o0 = fmaf(p, sv[j][lane],      o0);
            o1 = fmaf(p, sv[j][lane + 32], o1);
        }
        const size_t obase = ((size_t)b * NTOK + i) * C_ + (size_t)h * HD;
        __nv_bfloat16 hh, ll;
        split2(o0, hh, ll);
        ohi[obase + lane]      = hh;  olo[obase + lane]      = ll;
        split2(o1, hh, ll);
        ohi[obase + lane + 32] = hh;  olo[obase + lane + 32] = ll;
        __syncwarp();
    }
}

// ---------------------------------------------------------------------------
extern "C" void kernel_launch(void* const* d_in, const int* in_sizes, int n_in,
                              void* d_out, int out_size)
{
    const float* x      = (const float*)d_in[0];
    const float* pe     = (const float*)d_in[1];
    const float* mask   = (const float*)d_in[2];
    const float* w_qkv  = (const float*)d_in[3];
    const float* b_qkv  = (const float*)d_in[4];
    const float* w_proj = (const float*)d_in[5];
    const float* b_proj = (const float*)d_in[6];
    float* out = (float*)d_out;

    float*         qkv_buf; cudaGetSymbolAddress((void**)&qkv_buf, g_qkv);
    __nv_bfloat16 *xhi, *xlo, *whi, *wlo, *phi, *plo, *ahi, *alo;
    cudaGetSymbolAddress((void**)&xhi, g_xhi);
    cudaGetSymbolAddress((void**)&xlo, g_xlo);
    cudaGetSymbolAddress((void**)&whi, g_whi);
    cudaGetSymbolAddress((void**)&wlo, g_wlo);
    cudaGetSymbolAddress((void**)&phi, g_phi);
    cudaGetSymbolAddress((void**)&plo, g_plo);
    cudaGetSymbolAddress((void**)&ahi, g_ahi);
    cudaGetSymbolAddress((void**)&alo, g_alo);

    cudaFuncSetAttribute(gemm_bf16x3_kernel,
                         cudaFuncAttributeMaxDynamicSharedMemorySize, GEMM_SMEM);

    // 0) precompute bf16 splits
    {
        const size_t nx = (size_t)M_ * C_ / 4;
        split_x_pe_kernel<<<(unsigned)((nx + 255) / 256), 256>>>(x, pe, xhi, xlo);
        const size_t nw = (size_t)K3C * C_;
        split_w_kernel<<<(unsigned)((nw / 4 + 255) / 256), 256>>>(w_qkv, whi, wlo, nw);
        const size_t np = (size_t)C_ * C_;
        split_w_kernel<<<(unsigned)((np / 4 + 255) / 256), 256>>>(w_proj, phi, plo, np);
    }

    // 1) QKV projection: (M x 768) @ (768 x 2304)^T + bias -> g_qkv (fp32)
    {
        dim3 grid(K3C / 128, M_ / 128);
        gemm_bf16x3_kernel<<<grid, 256, GEMM_SMEM>>>(xhi, xlo, whi, wlo,
                                                     b_qkv, qkv_buf, K3C, C_);
    }

    // 2) Attention -> bf16 split output
    attention_kernel<<<B_ * H_, 256>>>(qkv_buf, mask, ahi, alo);

    // 3) Output projection -> d_out
    {
        dim3 grid(C_ / 128, M_ / 128);
        gemm_bf16x3_kernel<<<grid, 256, GEMM_SMEM>>>(ahi, alo, phi, plo,
                                                     b_proj, out, C_, C_);
    }
}

// round 4
// speedup vs baseline: 2.1658x; 1.0028x over previous
#include <cuda_runtime.h>
#include <cuda_bf16.h>
#include <math_constants.h>
#include <cstdint>

// Problem constants
#define B_   1024
#define NTOK 68
#define C_   768
#define H_   12
#define HD   64
#define M_   (B_ * NTOK)        // 69632
#define K3C  (3 * C_)           // 2304

// Scratch (__device__ globals; allocation-free rule)
__device__ float         g_qkv[(size_t)M_ * K3C];   // QKV output fp32
__device__ __nv_bfloat16 g_xhi[(size_t)M_ * C_];    // x+pe split
__device__ __nv_bfloat16 g_xlo[(size_t)M_ * C_];
__device__ __nv_bfloat16 g_whi[(size_t)K3C * C_];   // w_qkv split
__device__ __nv_bfloat16 g_wlo[(size_t)K3C * C_];
__device__ __nv_bfloat16 g_phi[(size_t)C_ * C_];    // w_proj split
__device__ __nv_bfloat16 g_plo[(size_t)C_ * C_];
__device__ __nv_bfloat16 g_ahi[(size_t)M_ * C_];    // attention out split
__device__ __nv_bfloat16 g_alo[(size_t)M_ * C_];

// ---------------------------------------------------------------------------
// helpers
// ---------------------------------------------------------------------------
static __device__ __forceinline__ uint32_t smem_u32(const void* p) {
    uint32_t a;
    asm("{ .reg .u64 t; cvta.to.shared.u64 t, %1; cvt.u32.u64 %0, t; }"
        : "=r"(a) : "l"(p));
    return a;
}

static __device__ __forceinline__ void split2(float v, __nv_bfloat16& h,
                                              __nv_bfloat16& l) {
    h = __float2bfloat16_rn(v);
    l = __float2bfloat16_rn(v - __bfloat162float(h));
}

#define CP16(dst, src) \
    asm volatile("cp.async.cg.shared.global [%0], [%1], 16;" \
                 :: "r"(dst), "l"(src))
#define CP_COMMIT() asm volatile("cp.async.commit_group;" ::: "memory")
#define CP_WAIT2()  asm volatile("cp.async.wait_group 2;"  ::: "memory")

#define LDSM_X4(r, addr) \
    asm volatile("ldmatrix.sync.aligned.m8n8.x4.shared.b16 {%0,%1,%2,%3}, [%4];" \
                 : "=r"((r)[0]), "=r"((r)[1]), "=r"((r)[2]), "=r"((r)[3]) \
                 : "r"(addr))

#define MMA_BF16(d, a, b0, b1) \
    asm volatile("mma.sync.aligned.m16n8k16.row.col.f32.bf16.bf16.f32 " \
                 "{%0,%1,%2,%3}, {%4,%5,%6,%7}, {%8,%9}, {%0,%1,%2,%3};" \
                 : "+f"((d)[0]), "+f"((d)[1]), "+f"((d)[2]), "+f"((d)[3]) \
                 : "r"((a)[0]), "r"((a)[1]), "r"((a)[2]), "r"((a)[3]), \
                   "r"(b0), "r"(b1))

// smem tile: 128 rows x 64 bytes (32 bf16/row), XOR swizzle (conflict-free
// ldmatrix). 4 stages x 4 tiles (Ahi, Alo, Bhi, Blo) x 8KB = 128KB.
static __device__ __forceinline__ uint32_t sw_off(int row, int c) {
    const int s = (row & 3) ^ ((row >> 2) & 3);
    return (uint32_t)(row * 64 + ((c ^ s) << 4));
}
#define TILE_ST(s, w) ((s) * 32768 + (w) * 8192)
#define GEMM_SMEM 131072

// ---------------------------------------------------------------------------
// split kernels (fp32 -> bf16 hi/lo pair)
// ---------------------------------------------------------------------------
__global__ void split_x_pe_kernel(const float* __restrict__ x,
                                  const float* __restrict__ pe,
                                  __nv_bfloat16* __restrict__ hi,
                                  __nv_bfloat16* __restrict__ lo)
{
    const size_t i4 = (size_t)blockIdx.x * blockDim.x + threadIdx.x;
    const size_t e  = i4 * 4;
    if (e >= (size_t)M_ * C_) return;
    const int row = (int)(e / C_);
    const int col = (int)(e % C_);
    const int tok = row % NTOK;

    float4 v = *reinterpret_cast<const float4*>(x + e);
    if (tok >= 4) {
        const float4 p = *reinterpret_cast<const float4*>(
            pe + (size_t)(tok + 28) * C_ + col);
        v.x += p.x; v.y += p.y; v.z += p.z; v.w += p.w;
    }
    __nv_bfloat16 h0, l0, h1, l1, h2, l2, h3, l3;
    split2(v.x, h0, l0); split2(v.y, h1, l1);
    split2(v.z, h2, l2); split2(v.w, h3, l3);
    __nv_bfloat162* hp = reinterpret_cast<__nv_bfloat162*>(hi + e);
    __nv_bfloat162* lp = reinterpret_cast<__nv_bfloat162*>(lo + e);
    hp[0] = __nv_bfloat162(h0, h1); hp[1] = __nv_bfloat162(h2, h3);
    lp[0] = __nv_bfloat162(l0, l1); lp[1] = __nv_bfloat162(l2, l3);
}

__global__ void split_w_kernel(const float* __restrict__ w,
                               __nv_bfloat16* __restrict__ hi,
                               __nv_bfloat16* __restrict__ lo,
                               size_t n_elem)
{
    const size_t i4 = (size_t)blockIdx.x * blockDim.x + threadIdx.x;
    const size_t e  = i4 * 4;
    if (e >= n_elem) return;
    const float4 v = *reinterpret_cast<const float4*>(w + e);
    __nv_bfloat16 h0, l0, h1, l1, h2, l2, h3, l3;
    split2(v.x, h0, l0); split2(v.y, h1, l1);
    split2(v.z, h2, l2); split2(v.w, h3, l3);
    __nv_bfloat162* hp = reinterpret_cast<__nv_bfloat162*>(hi + e);
    __nv_bfloat162* lp = reinterpret_cast<__nv_bfloat162*>(lo + e);
    hp[0] = __nv_bfloat162(h0, h1); hp[1] = __nv_bfloat162(h2, h3);
    lp[0] = __nv_bfloat162(l0, l1); lp[1] = __nv_bfloat162(l2, l3);
}

// ---------------------------------------------------------------------------
// GEMM: C[m][n] = sum_k (Ahi+Alo)[m][k] * (Bhi+Blo)[n][k] + bias[n]
// D = Ahi*Bhi + Ahi*Blo + Alo*Bhi  (bf16 mma.sync, fp32 accum).
// CTA 128x128, 8 warps (2m x 4n), warp tile 64x32, K-chunk 32, 4 stages,
// register fragments double-buffered at half-chunk (k=16) granularity.
// ---------------------------------------------------------------------------
__global__ __launch_bounds__(256)
void gemm_bf16x3_kernel(const __nv_bfloat16* __restrict__ Ahi,
                        const __nv_bfloat16* __restrict__ Alo,
                        const __nv_bfloat16* __restrict__ Bhi,
                        const __nv_bfloat16* __restrict__ Blo,
                        const float* __restrict__ bias,
                        float* __restrict__ Cout,
                        int N, int K)
{
    extern __shared__ char smem[];
    const uint32_t sb = smem_u32(smem);

    const int tid  = threadIdx.x;
    const int wid  = tid >> 5;
    const int lane = tid & 31;
    const int cN   = blockIdx.x;
    const int cM   = blockIdx.y;
    const int wm   = wid & 1;    // 0..1
    const int wn   = wid >> 1;   // 0..3

    // ---- cp.async geometry: 2 x 16B per thread per tile ----
    const int r0 = tid >> 2,         c0 = tid & 3;
    const int r1 = (tid + 256) >> 2, c1 = (tid + 256) & 3;
    const uint32_t so0 = sw_off(r0, c0);
    const uint32_t so1 = sw_off(r1, c1);
    const __nv_bfloat16* gAh0 = Ahi + (size_t)(cM * 128 + r0) * K + c0 * 8;
    const __nv_bfloat16* gAh1 = Ahi + (size_t)(cM * 128 + r1) * K + c1 * 8;
    const __nv_bfloat16* gAl0 = Alo + (size_t)(cM * 128 + r0) * K + c0 * 8;
    const __nv_bfloat16* gAl1 = Alo + (size_t)(cM * 128 + r1) * K + c1 * 8;
    const __nv_bfloat16* gBh0 = Bhi + (size_t)(cN * 128 + r0) * K + c0 * 8;
    const __nv_bfloat16* gBh1 = Bhi + (size_t)(cN * 128 + r1) * K + c1 * 8;
    const __nv_bfloat16* gBl0 = Blo + (size_t)(cN * 128 + r0) * K + c0 * 8;
    const __nv_bfloat16* gBl1 = Blo + (size_t)(cN * 128 + r1) * K + c1 * 8;

#define LOAD_STAGE(s, k0)                                            \
    do {                                                              \
        CP16(sb + TILE_ST(s, 0) + so0, gAh0 + (k0));                  \
        CP16(sb + TILE_ST(s, 0) + so1, gAh1 + (k0));                  \
        CP16(sb + TILE_ST(s, 1) + so0, gAl0 + (k0));                  \
        CP16(sb + TILE_ST(s, 1) + so1, gAl1 + (k0));                  \
        CP16(sb + TILE_ST(s, 2) + so0, gBh0 + (k0));                  \
        CP16(sb + TILE_ST(s, 2) + so1, gBh1 + (k0));                  \
        CP16(sb + TILE_ST(s, 3) + so0, gBl0 + (k0));                  \
        CP16(sb + TILE_ST(s, 3) + so1, gBl1 + (k0));                  \
    } while (0)

    // per-warp ldmatrix base offsets
    const int arow = wm * 64 + (lane & 15);   // + mf*16
    const int brow = wn * 32 + (lane & 15);   // + bf*16
    const int chi  = lane >> 4;               // 16B column sub-chunk

#define FRAG_LOAD(Ah_, Al_, Bh_, Bl_, st, t)                                 \
    do {                                                                      \
        _Pragma("unroll")                                                     \
        for (int mf = 0; mf < 4; mf++) {                                      \
            const uint32_t ao = sw_off(arow + mf * 16, 2 * (t) + chi);        \
            LDSM_X4(Ah_[mf], sb + TILE_ST(st, 0) + ao);                       \
            LDSM_X4(Al_[mf], sb + TILE_ST(st, 1) + ao);                       \
        }                                                                     \
        _Pragma("unroll")                                                     \
        for (int bf = 0; bf < 2; bf++) {                                      \
            const uint32_t bo = sw_off(brow + bf * 16, 2 * (t) + chi);        \
            LDSM_X4(Bh_[bf], sb + TILE_ST(st, 2) + bo);                       \
            LDSM_X4(Bl_[bf], sb + TILE_ST(st, 3) + bo);                       \
        }                                                                     \
    } while (0)

#define MMA_ALL(Ah_, Al_, Bh_, Bl_)                                          \
    do {                                                                      \
        _Pragma("unroll")                                                     \
        for (int mf = 0; mf < 4; mf++) {                                      \
            _Pragma("unroll")                                                 \
            for (int nf = 0; nf < 4; nf++) {                                  \
                const int g = nf >> 1, h = nf & 1;                            \
                const uint32_t bh0 = Bh_[g][h], bh1 = Bh_[g][h + 2];          \
                const uint32_t bl0 = Bl_[g][h], bl1 = Bl_[g][h + 2];          \
                MMA_BF16(acc[mf][nf], Ah_[mf], bh0, bh1);                     \
                MMA_BF16(acc[mf][nf], Ah_[mf], bl0, bl1);                     \
                MMA_BF16(acc[mf][nf], Al_[mf], bh0, bh1);                     \
            }                                                                 \
        }                                                                     \
    } while (0)

    float acc[4][4][4];
#pragma unroll
    for (int i = 0; i < 4; i++)
#pragma unroll
        for (int j = 0; j < 4; j++)
#pragma unroll
            for (int r = 0; r < 4; r++) acc[i][j][r] = 0.0f;

    const int NC = K >> 5;   // 24

    // ---- prologue: 3 stages in flight ----
    LOAD_STAGE(0, 0);   CP_COMMIT();
    LOAD_STAGE(1, 32);  CP_COMMIT();
    LOAD_STAGE(2, 64);  CP_COMMIT();
    CP_WAIT2();
    __syncthreads();

    uint32_t Ah0[4][4], Al0[4][4], Bh0[2][4], Bl0[2][4];
    uint32_t Ah1[4][4], Al1[4][4], Bh1[2][4], Bl1[2][4];
    FRAG_LOAD(Ah0, Al0, Bh0, Bl0, 0, 0);

    for (int kc = 0; kc < NC; kc++) {
        const int cur = kc & 3;

        // prefetch second half of this chunk, then compute first half
        FRAG_LOAD(Ah1, Al1, Bh1, Bl1, cur, 1);
        MMA_ALL(Ah0, Al0, Bh0, Bl0);

        // keep the ring 3 ahead
        if (kc + 3 < NC) LOAD_STAGE((kc + 3) & 3, (kc + 3) * 32);
        CP_COMMIT();

        if (kc + 1 < NC) {
            CP_WAIT2();
            __syncthreads();
            // prefetch first half of next chunk, then compute second half
            FRAG_LOAD(Ah0, Al0, Bh0, Bl0, (kc + 1) & 3, 0);
        }
        MMA_ALL(Ah1, Al1, Bh1, Bl1);
    }

    // ---- epilogue: bias + fp32 store ----
#pragma unroll
    for (int mf = 0; mf < 4; mf++) {
        const int row = cM * 128 + wm * 64 + mf * 16 + (lane >> 2);
#pragma unroll
        for (int nf = 0; nf < 4; nf++) {
            const int col = cN * 128 + wn * 32 + nf * 8 + (lane & 3) * 2;
            const float2 bb = *reinterpret_cast<const float2*>(bias + col);
            float2 o0, o1;
            o0.x = acc[mf][nf][0] + bb.x;  o0.y = acc[mf][nf][1] + bb.y;
            o1.x = acc[mf][nf][2] + bb.x;  o1.y = acc[mf][nf][3] + bb.y;
            *reinterpret_cast<float2*>(Cout + (size_t)row * N + col) = o0;
            *reinterpret_cast<float2*>(Cout + (size_t)(row + 8) * N + col) = o1;
        }
    }
#undef LOAD_STAGE
#undef FRAG_LOAD
#undef MMA_ALL
}

// ---------------------------------------------------------------------------
// Attention: one CTA per (b, h). Writes bf16 hi/lo split of output directly.
// ---------------------------------------------------------------------------
__global__ __launch_bounds__(256)
void attention_kernel(const float* __restrict__ qkv,
                      const float* __restrict__ mask,
                      __nv_bfloat16* __restrict__ ohi,
                      __nv_bfloat16* __restrict__ olo)
{
    __shared__ float sk[NTOK][HD + 1];
    __shared__ float sv[NTOK][HD + 1];
    __shared__ float sq[8][HD];
    __shared__ float sp[8][NTOK];

    const int bh = blockIdx.x;
    const int b  = bh / H_;
    const int h  = bh % H_;
    const int tid  = threadIdx.x;
    const int warp = tid >> 5;
    const int lane = tid & 31;

    const size_t base = (size_t)b * NTOK * K3C + (size_t)h * HD;
    for (int idx = tid; idx < NTOK * HD; idx += 256) {
        const int j = idx / HD, d = idx % HD;
        sk[j][d] = qkv[base + (size_t)j * K3C + C_ + d];
        sv[j][d] = qkv[base + (size_t)j * K3C + 2 * C_ + d];
    }
    __syncthreads();

    const float scale = 0.125f;
    const float* mrow_base = mask + (size_t)b * NTOK * NTOK;

    for (int i = warp; i < NTOK; i += 8) {
        sq[warp][lane]      = qkv[base + (size_t)i * K3C + lane]      * scale;
        sq[warp][lane + 32] = qkv[base + (size_t)i * K3C + lane + 32] * scale;
        __syncwarp();

        float s[3];
#pragma unroll
        for (int t = 0; t < 3; t++) {
            const int j = lane + 32 * t;
            if (j < NTOK) {
                float a0 = 0.0f, a1 = 0.0f;
#pragma unroll
                for (int d = 0; d < HD; d += 2) {
                    a0 = fmaf(sq[warp][d],     sk[j][d],     a0);
                    a1 = fmaf(sq[warp][d + 1], sk[j][d + 1], a1);
                }
                s[t] = a0 + a1 + mrow_base[(size_t)i * NTOK + j];
            } else {
                s[t] = -CUDART_INF_F;
            }
        }

        float mx = fmaxf(fmaxf(s[0], s[1]), s[2]);
#pragma unroll
        for (int off = 16; off > 0; off >>= 1)
            mx = fmaxf(mx, __shfl_xor_sync(0xffffffffu, mx, off));

        float e[3], sum = 0.0f;
#pragma unroll
        for (int t = 0; t < 3; t++) {
            e[t] = (lane + 32 * t < NTOK) ? __expf(s[t] - mx) : 0.0f;
            sum += e[t];
        }
#pragma unroll
        for (int off = 16; off > 0; off >>= 1)
            sum += __shfl_xor_sync(0xffffffffu, sum, off);
        const float inv = 1.0f / sum;

#pragma unroll
        for (int t = 0; t < 3; t++) {
            const int j = lane + 32 * t;
            if (j < NTOK) sp[warp][j] = e[t] * inv;
        }
        __syncwarp();

        float o0a = 0.0f, o0b = 0.0f, o1a = 0.0f, o1b = 0.0f;
#pragma unroll
        for (int j = 0; j < NTOK; j += 2) {
            const float p0 = sp[warp][j], p1 = sp[warp][j + 1];
            o0a = fmaf(p0, sv[j][lane],          o0a);
            o0b = fmaf(p1, sv[j + 1][lane],      o0b);
            o1a = fmaf(p0, sv[j][lane + 32],     o1a);
            o1b = fmaf(p1, sv[j + 1][lane + 32], o1b);
        }
        const size_t obase = ((size_t)b * NTOK + i) * C_ + (size_t)h * HD;
        __nv_bfloat16 hh, ll;
        split2(o0a + o0b, hh, ll);
        ohi[obase + lane]      = hh;  olo[obase + lane]      = ll;
        split2(o1a + o1b, hh, ll);
        ohi[obase + lane + 32] = hh;  olo[obase + lane + 32] = ll;
        __syncwarp();
    }
}

// ---------------------------------------------------------------------------
extern "C" void kernel_launch(void* const* d_in, const int* in_sizes, int n_in,
                              void* d_out, int out_size)
{
    const float* x      = (const float*)d_in[0];
    const float* pe     = (const float*)d_in[1];
    const float* mask   = (const float*)d_in[2];
    const float* w_qkv  = (const float*)d_in[3];
    const float* b_qkv  = (const float*)d_in[4];
    const float* w_proj = (const float*)d_in[5];
    const float* b_proj = (const float*)d_in[6];
    float* out = (float*)d_out;

    float*         qkv_buf; cudaGetSymbolAddress((void**)&qkv_buf, g_qkv);
    __nv_bfloat16 *xhi, *xlo, *whi, *wlo, *phi, *plo, *ahi, *alo;
    cudaGetSymbolAddress((void**)&xhi, g_xhi);
    cudaGetSymbolAddress((void**)&xlo, g_xlo);
    cudaGetSymbolAddress((void**)&whi, g_whi);
    cudaGetSymbolAddress((void**)&wlo, g_wlo);
    cudaGetSymbolAddress((void**)&phi, g_phi);
    cudaGetSymbolAddress((void**)&plo, g_plo);
    cudaGetSymbolAddress((void**)&ahi, g_ahi);
    cudaGetSymbolAddress((void**)&alo, g_alo);

    cudaFuncSetAttribute(gemm_bf16x3_kernel,
                         cudaFuncAttributeMaxDynamicSharedMemorySize, GEMM_SMEM);

    // 0) precompute bf16 splits
    {
        const size_t nx = (size_t)M_ * C_ / 4;
        split_x_pe_kernel<<<(unsigned)((nx + 255) / 256), 256>>>(x, pe, xhi, xlo);
        const size_t nw = (size_t)K3C * C_;
        split_w_kernel<<<(unsigned)((nw / 4 + 255) / 256), 256>>>(w_qkv, whi, wlo, nw);
        const size_t np = (size_t)C_ * C_;
        split_w_kernel<<<(unsigned)((np / 4 + 255) / 256), 256>>>(w_proj, phi, plo, np);
    }

    // 1) QKV projection: (M x 768) @ (768 x 2304)^T + bias -> g_qkv (fp32)
    {
        dim3 grid(K3C / 128, M_ / 128);
        gemm_bf16x3_kernel<<<grid, 256, GEMM_SMEM>>>(xhi, xlo, whi, wlo,
                                                     b_qkv, qkv_buf, K3C, C_);
    }

    // 2) Attention -> bf16 split output
    attention_kernel<<<B_ * H_, 256>>>(qkv_buf, mask, ahi, alo);

    // 3) Output projection -> d_out
    {
        dim3 grid(C_ / 128, M_ / 128);
        gemm_bf16x3_kernel<<<grid, 256, GEMM_SMEM>>>(ahi, alo, phi, plo,
                                                     b_proj, out, C_, C_);
    }
}

// round 5
// speedup vs baseline: 2.4397x; 1.1265x over previous
#include <cuda_runtime.h>
#include <cuda_bf16.h>
#include <math_constants.h>
#include <cstdint>

// Problem constants
#define B_   1024
#define NTOK 68
#define C_   768
#define H_   12
#define HD   64
#define M_   (B_ * NTOK)        // 69632
#define K3C  (3 * C_)           // 2304

// Scratch (__device__ globals; allocation-free rule)
__device__ float         g_qkv[(size_t)M_ * K3C];   // QKV output fp32
__device__ __nv_bfloat16 g_xhi[(size_t)M_ * C_];    // x+pe split
__device__ __nv_bfloat16 g_xlo[(size_t)M_ * C_];
__device__ __nv_bfloat16 g_whi[(size_t)K3C * C_];   // w_qkv split
__device__ __nv_bfloat16 g_wlo[(size_t)K3C * C_];
__device__ __nv_bfloat16 g_phi[(size_t)C_ * C_];    // w_proj split
__device__ __nv_bfloat16 g_plo[(size_t)C_ * C_];
__device__ __nv_bfloat16 g_ahi[(size_t)M_ * C_];    // attention out split
__device__ __nv_bfloat16 g_alo[(size_t)M_ * C_];

// ---------------------------------------------------------------------------
// helpers
// ---------------------------------------------------------------------------
static __device__ __forceinline__ uint32_t smem_u32(const void* p) {
    uint32_t a;
    asm("{ .reg .u64 t; cvta.to.shared.u64 t, %1; cvt.u32.u64 %0, t; }"
        : "=r"(a) : "l"(p));
    return a;
}

static __device__ __forceinline__ void split2(float v, __nv_bfloat16& h,
                                              __nv_bfloat16& l) {
    h = __float2bfloat16_rn(v);
    l = __float2bfloat16_rn(v - __bfloat162float(h));
}

#define CP16(dst, src) \
    asm volatile("cp.async.cg.shared.global [%0], [%1], 16;" \
                 :: "r"(dst), "l"(src))
#define CP_COMMIT() asm volatile("cp.async.commit_group;" ::: "memory")
#define CP_WAIT2()  asm volatile("cp.async.wait_group 2;"  ::: "memory")

#define LDSM_X4(r, addr) \
    asm volatile("ldmatrix.sync.aligned.m8n8.x4.shared.b16 {%0,%1,%2,%3}, [%4];" \
                 : "=r"((r)[0]), "=r"((r)[1]), "=r"((r)[2]), "=r"((r)[3]) \
                 : "r"(addr))

#define MMA_BF16(d, a, b0, b1) \
    asm volatile("mma.sync.aligned.m16n8k16.row.col.f32.bf16.bf16.f32 " \
                 "{%0,%1,%2,%3}, {%4,%5,%6,%7}, {%8,%9}, {%0,%1,%2,%3};" \
                 : "+f"((d)[0]), "+f"((d)[1]), "+f"((d)[2]), "+f"((d)[3]) \
                 : "r"((a)[0]), "r"((a)[1]), "r"((a)[2]), "r"((a)[3]), \
                   "r"(b0), "r"(b1))

// smem tile: 128 rows x 64 bytes (32 bf16/row), XOR swizzle (conflict-free
// ldmatrix). 4 stages x 4 tiles (Ahi, Alo, Bhi, Blo) x 8KB = 128KB.
static __device__ __forceinline__ uint32_t sw_off(int row, int c) {
    const int s = (row & 3) ^ ((row >> 2) & 3);
    return (uint32_t)(row * 64 + ((c ^ s) << 4));
}
#define TILE_ST(s, w) ((s) * 32768 + (w) * 8192)
#define GEMM_SMEM 131072

// ---------------------------------------------------------------------------
// split kernels (fp32 -> bf16 hi/lo pair)
// ---------------------------------------------------------------------------
__global__ void split_x_pe_kernel(const float* __restrict__ x,
                                  const float* __restrict__ pe,
                                  __nv_bfloat16* __restrict__ hi,
                                  __nv_bfloat16* __restrict__ lo)
{
    const size_t i4 = (size_t)blockIdx.x * blockDim.x + threadIdx.x;
    const size_t e  = i4 * 4;
    if (e >= (size_t)M_ * C_) return;
    const int row = (int)(e / C_);
    const int col = (int)(e % C_);
    const int tok = row % NTOK;

    float4 v = *reinterpret_cast<const float4*>(x + e);
    if (tok >= 4) {
        const float4 p = *reinterpret_cast<const float4*>(
            pe + (size_t)(tok + 28) * C_ + col);
        v.x += p.x; v.y += p.y; v.z += p.z; v.w += p.w;
    }
    __nv_bfloat16 h0, l0, h1, l1, h2, l2, h3, l3;
    split2(v.x, h0, l0); split2(v.y, h1, l1);
    split2(v.z, h2, l2); split2(v.w, h3, l3);
    __nv_bfloat162* hp = reinterpret_cast<__nv_bfloat162*>(hi + e);
    __nv_bfloat162* lp = reinterpret_cast<__nv_bfloat162*>(lo + e);
    hp[0] = __nv_bfloat162(h0, h1); hp[1] = __nv_bfloat162(h2, h3);
    lp[0] = __nv_bfloat162(l0, l1); lp[1] = __nv_bfloat162(l2, l3);
}

__global__ void split_w_kernel(const float* __restrict__ w,
                               __nv_bfloat16* __restrict__ hi,
                               __nv_bfloat16* __restrict__ lo,
                               size_t n_elem)
{
    const size_t i4 = (size_t)blockIdx.x * blockDim.x + threadIdx.x;
    const size_t e  = i4 * 4;
    if (e >= n_elem) return;
    const float4 v = *reinterpret_cast<const float4*>(w + e);
    __nv_bfloat16 h0, l0, h1, l1, h2, l2, h3, l3;
    split2(v.x, h0, l0); split2(v.y, h1, l1);
    split2(v.z, h2, l2); split2(v.w, h3, l3);
    __nv_bfloat162* hp = reinterpret_cast<__nv_bfloat162*>(hi + e);
    __nv_bfloat162* lp = reinterpret_cast<__nv_bfloat162*>(lo + e);
    hp[0] = __nv_bfloat162(h0, h1); hp[1] = __nv_bfloat162(h2, h3);
    lp[0] = __nv_bfloat162(l0, l1); lp[1] = __nv_bfloat162(l2, l3);
}

// ---------------------------------------------------------------------------
// GEMM: C[m][n] = sum_k (Ahi+Alo)[m][k] * (Bhi+Blo)[n][k] + bias[n]
// D = Ahi*Bhi + Ahi*Blo + Alo*Bhi  (bf16 mma.sync, fp32 accum).
// CTA 128x128, 8 warps (2m x 4n), warp tile 64x32, K-chunk 32, 4 stages.
// MMA schedule is TERM-MAJOR: each pass touches all 16 accumulators before
// any accumulator is revisited -> no RAW chains on the tensor pipe.
// ---------------------------------------------------------------------------
__global__ __launch_bounds__(256)
void gemm_bf16x3_kernel(const __nv_bfloat16* __restrict__ Ahi,
                        const __nv_bfloat16* __restrict__ Alo,
                        const __nv_bfloat16* __restrict__ Bhi,
                        const __nv_bfloat16* __restrict__ Blo,
                        const float* __restrict__ bias,
                        float* __restrict__ Cout,
                        int N, int K)
{
    extern __shared__ char smem[];
    const uint32_t sb = smem_u32(smem);

    const int tid  = threadIdx.x;
    const int wid  = tid >> 5;
    const int lane = tid & 31;
    const int cN   = blockIdx.x;
    const int cM   = blockIdx.y;
    const int wm   = wid & 1;    // 0..1
    const int wn   = wid >> 1;   // 0..3

    // ---- cp.async geometry: 2 x 16B per thread per tile ----
    const int r0 = tid >> 2,         c0 = tid & 3;
    const int r1 = (tid + 256) >> 2, c1 = (tid + 256) & 3;
    const uint32_t so0 = sw_off(r0, c0);
    const uint32_t so1 = sw_off(r1, c1);
    const __nv_bfloat16* gAh0 = Ahi + (size_t)(cM * 128 + r0) * K + c0 * 8;
    const __nv_bfloat16* gAh1 = Ahi + (size_t)(cM * 128 + r1) * K + c1 * 8;
    const __nv_bfloat16* gAl0 = Alo + (size_t)(cM * 128 + r0) * K + c0 * 8;
    const __nv_bfloat16* gAl1 = Alo + (size_t)(cM * 128 + r1) * K + c1 * 8;
    const __nv_bfloat16* gBh0 = Bhi + (size_t)(cN * 128 + r0) * K + c0 * 8;
    const __nv_bfloat16* gBh1 = Bhi + (size_t)(cN * 128 + r1) * K + c1 * 8;
    const __nv_bfloat16* gBl0 = Blo + (size_t)(cN * 128 + r0) * K + c0 * 8;
    const __nv_bfloat16* gBl1 = Blo + (size_t)(cN * 128 + r1) * K + c1 * 8;

#define LOAD_STAGE(s, k0)                                            \
    do {                                                              \
        CP16(sb + TILE_ST(s, 0) + so0, gAh0 + (k0));                  \
        CP16(sb + TILE_ST(s, 0) + so1, gAh1 + (k0));                  \
        CP16(sb + TILE_ST(s, 1) + so0, gAl0 + (k0));                  \
        CP16(sb + TILE_ST(s, 1) + so1, gAl1 + (k0));                  \
        CP16(sb + TILE_ST(s, 2) + so0, gBh0 + (k0));                  \
        CP16(sb + TILE_ST(s, 2) + so1, gBh1 + (k0));                  \
        CP16(sb + TILE_ST(s, 3) + so0, gBl0 + (k0));                  \
        CP16(sb + TILE_ST(s, 3) + so1, gBl1 + (k0));                  \
    } while (0)

    // per-warp ldmatrix base offsets
    const int arow = wm * 64 + (lane & 15);   // + mf*16
    const int brow = wn * 32 + (lane & 15);   // + bf*16
    const int chi  = lane >> 4;               // 16B column sub-chunk

#define FRAG_LOAD(Ah_, Al_, Bh_, Bl_, st, t)                                 \
    do {                                                                      \
        _Pragma("unroll")                                                     \
        for (int mf = 0; mf < 4; mf++) {                                      \
            const uint32_t ao = sw_off(arow + mf * 16, 2 * (t) + chi);        \
            LDSM_X4(Ah_[mf], sb + TILE_ST(st, 0) + ao);                       \
            LDSM_X4(Al_[mf], sb + TILE_ST(st, 1) + ao);                       \
        }                                                                     \
        _Pragma("unroll")                                                     \
        for (int bf = 0; bf < 2; bf++) {                                      \
            const uint32_t bo = sw_off(brow + bf * 16, 2 * (t) + chi);        \
            LDSM_X4(Bh_[bf], sb + TILE_ST(st, 2) + bo);                       \
            LDSM_X4(Bl_[bf], sb + TILE_ST(st, 3) + bo);                       \
        }                                                                     \
    } while (0)

// term-major: 3 passes of 16 independent-accumulator MMAs each
#define MMA_ALL(Ah_, Al_, Bh_, Bl_)                                          \
    do {                                                                      \
        _Pragma("unroll")                                                     \
        for (int mf = 0; mf < 4; mf++) {                                      \
            _Pragma("unroll")                                                 \
            for (int nf = 0; nf < 4; nf++) {                                  \
                const int g = nf >> 1, h = nf & 1;                            \
                MMA_BF16(acc[mf][nf], Ah_[mf], Bh_[g][h], Bh_[g][h + 2]);     \
            }                                                                 \
        }                                                                     \
        _Pragma("unroll")                                                     \
        for (int mf = 0; mf < 4; mf++) {                                      \
            _Pragma("unroll")                                                 \
            for (int nf = 0; nf < 4; nf++) {                                  \
                const int g = nf >> 1, h = nf & 1;                            \
                MMA_BF16(acc[mf][nf], Ah_[mf], Bl_[g][h], Bl_[g][h + 2]);     \
            }                                                                 \
        }                                                                     \
        _Pragma("unroll")                                                     \
        for (int mf = 0; mf < 4; mf++) {                                      \
            _Pragma("unroll")                                                 \
            for (int nf = 0; nf < 4; nf++) {                                  \
                const int g = nf >> 1, h = nf & 1;                            \
                MMA_BF16(acc[mf][nf], Al_[mf], Bh_[g][h], Bh_[g][h + 2]);     \
            }                                                                 \
        }                                                                     \
    } while (0)

    float acc[4][4][4];
#pragma unroll
    for (int i = 0; i < 4; i++)
#pragma unroll
        for (int j = 0; j < 4; j++)
#pragma unroll
            for (int r = 0; r < 4; r++) acc[i][j][r] = 0.0f;

    const int NC = K >> 5;   // 24

    // ---- prologue: 3 stages in flight ----
    LOAD_STAGE(0, 0);   CP_COMMIT();
    LOAD_STAGE(1, 32);  CP_COMMIT();
    LOAD_STAGE(2, 64);  CP_COMMIT();
    CP_WAIT2();
    __syncthreads();

    uint32_t Ah0[4][4], Al0[4][4], Bh0[2][4], Bl0[2][4];
    uint32_t Ah1[4][4], Al1[4][4], Bh1[2][4], Bl1[2][4];
    FRAG_LOAD(Ah0, Al0, Bh0, Bl0, 0, 0);

    for (int kc = 0; kc < NC; kc++) {
        const int cur = kc & 3;

        // prefetch second half of this chunk, then compute first half
        FRAG_LOAD(Ah1, Al1, Bh1, Bl1, cur, 1);
        MMA_ALL(Ah0, Al0, Bh0, Bl0);

        // keep the ring 3 ahead
        if (kc + 3 < NC) LOAD_STAGE((kc + 3) & 3, (kc + 3) * 32);
        CP_COMMIT();

        if (kc + 1 < NC) {
            CP_WAIT2();
            __syncthreads();
            // prefetch first half of next chunk, then compute second half
            FRAG_LOAD(Ah0, Al0, Bh0, Bl0, (kc + 1) & 3, 0);
        }
        MMA_ALL(Ah1, Al1, Bh1, Bl1);
    }

    // ---- epilogue: bias + fp32 store ----
#pragma unroll
    for (int mf = 0; mf < 4; mf++) {
        const int row = cM * 128 + wm * 64 + mf * 16 + (lane >> 2);
#pragma unroll
        for (int nf = 0; nf < 4; nf++) {
            const int col = cN * 128 + wn * 32 + nf * 8 + (lane & 3) * 2;
            const float2 bb = *reinterpret_cast<const float2*>(bias + col);
            float2 o0, o1;
            o0.x = acc[mf][nf][0] + bb.x;  o0.y = acc[mf][nf][1] + bb.y;
            o1.x = acc[mf][nf][2] + bb.x;  o1.y = acc[mf][nf][3] + bb.y;
            *reinterpret_cast<float2*>(Cout + (size_t)row * N + col) = o0;
            *reinterpret_cast<float2*>(Cout + (size_t)(row + 8) * N + col) = o1;
        }
    }
#undef LOAD_STAGE
#undef FRAG_LOAD
#undef MMA_ALL
}

// ---------------------------------------------------------------------------
// Attention: one CTA per (b, h). Writes bf16 hi/lo split of output directly.
// ---------------------------------------------------------------------------
__global__ __launch_bounds__(256)
void attention_kernel(const float* __restrict__ qkv,
                      const float* __restrict__ mask,
                      __nv_bfloat16* __restrict__ ohi,
                      __nv_bfloat16* __restrict__ olo)
{
    __shared__ float sk[NTOK][HD + 1];
    __shared__ float sv[NTOK][HD + 1];
    __shared__ float sq[8][HD];
    __shared__ float sp[8][NTOK];

    const int bh = blockIdx.x;
    const int b  = bh / H_;
    const int h  = bh % H_;
    const int tid  = threadIdx.x;
    const int warp = tid >> 5;
    const int lane = tid & 31;

    const size_t base = (size_t)b * NTOK * K3C + (size_t)h * HD;
    for (int idx = tid; idx < NTOK * HD; idx += 256) {
        const int j = idx / HD, d = idx % HD;
        sk[j][d] = qkv[base + (size_t)j * K3C + C_ + d];
        sv[j][d] = qkv[base + (size_t)j * K3C + 2 * C_ + d];
    }
    __syncthreads();

    const float scale = 0.125f;
    const float* mrow_base = mask + (size_t)b * NTOK * NTOK;

    for (int i = warp; i < NTOK; i += 8) {
        sq[warp][lane]      = qkv[base + (size_t)i * K3C + lane]      * scale;
        sq[warp][lane + 32] = qkv[base + (size_t)i * K3C + lane + 32] * scale;
        __syncwarp();

        float s[3];
#pragma unroll
        for (int t = 0; t < 3; t++) {
            const int j = lane + 32 * t;
            if (j < NTOK) {
                float a0 = 0.0f, a1 = 0.0f;
#pragma unroll
                for (int d = 0; d < HD; d += 2) {
                    a0 = fmaf(sq[warp][d],     sk[j][d],     a0);
                    a1 = fmaf(sq[warp][d + 1], sk[j][d + 1], a1);
                }
                s[t] = a0 + a1 + mrow_base[(size_t)i * NTOK + j];
            } else {
                s[t] = -CUDART_INF_F;
            }
        }

        float mx = fmaxf(fmaxf(s[0], s[1]), s[2]);
#pragma unroll
        for (int off = 16; off > 0; off >>= 1)
            mx = fmaxf(mx, __shfl_xor_sync(0xffffffffu, mx, off));

        float e[3], sum = 0.0f;
#pragma unroll
        for (int t = 0; t < 3; t++) {
            e[t] = (lane + 32 * t < NTOK) ? __expf(s[t] - mx) : 0.0f;
            sum += e[t];
        }
#pragma unroll
        for (int off = 16; off > 0; off >>= 1)
            sum += __shfl_xor_sync(0xffffffffu, sum, off);
        const float inv = 1.0f / sum;

#pragma unroll
        for (int t = 0; t < 3; t++) {
            const int j = lane + 32 * t;
            if (j < NTOK) sp[warp][j] = e[t] * inv;
        }
        __syncwarp();

        float o0a = 0.0f, o0b = 0.0f, o1a = 0.0f, o1b = 0.0f;
#pragma unroll
        for (int j = 0; j < NTOK; j += 2) {
            const float p0 = sp[warp][j], p1 = sp[warp][j + 1];
            o0a = fmaf(p0, sv[j][lane],          o0a);
            o0b = fmaf(p1, sv[j + 1][lane],      o0b);
            o1a = fmaf(p0, sv[j][lane + 32],     o1a);
            o1b = fmaf(p1, sv[j + 1][lane + 32], o1b);
        }
        const size_t obase = ((size_t)b * NTOK + i) * C_ + (size_t)h * HD;
        __nv_bfloat16 hh, ll;
        split2(o0a + o0b, hh, ll);
        ohi[obase + lane]      = hh;  olo[obase + lane]      = ll;
        split2(o1a + o1b, hh, ll);
        ohi[obase + lane + 32] = hh;  olo[obase + lane + 32] = ll;
        __syncwarp();
    }
}

// ---------------------------------------------------------------------------
extern "C" void kernel_launch(void* const* d_in, const int* in_sizes, int n_in,
                              void* d_out, int out_size)
{
    const float* x      = (const float*)d_in[0];
    const float* pe     = (const float*)d_in[1];
    const float* mask   = (const float*)d_in[2];
    const float* w_qkv  = (const float*)d_in[3];
    const float* b_qkv  = (const float*)d_in[4];
    const float* w_proj = (const float*)d_in[5];
    const float* b_proj = (const float*)d_in[6];
    float* out = (float*)d_out;

    float*         qkv_buf; cudaGetSymbolAddress((void**)&qkv_buf, g_qkv);
    __nv_bfloat16 *xhi, *xlo, *whi, *wlo, *phi, *plo, *ahi, *alo;
    cudaGetSymbolAddress((void**)&xhi, g_xhi);
    cudaGetSymbolAddress((void**)&xlo, g_xlo);
    cudaGetSymbolAddress((void**)&whi, g_whi);
    cudaGetSymbolAddress((void**)&wlo, g_wlo);
    cudaGetSymbolAddress((void**)&phi, g_phi);
    cudaGetSymbolAddress((void**)&plo, g_plo);
    cudaGetSymbolAddress((void**)&ahi, g_ahi);
    cudaGetSymbolAddress((void**)&alo, g_alo);

    cudaFuncSetAttribute(gemm_bf16x3_kernel,
                         cudaFuncAttributeMaxDynamicSharedMemorySize, GEMM_SMEM);

    // 0) precompute bf16 splits
    {
        const size_t nx = (size_t)M_ * C_ / 4;
        split_x_pe_kernel<<<(unsigned)((nx + 255) / 256), 256>>>(x, pe, xhi, xlo);
        const size_t nw = (size_t)K3C * C_;
        split_w_kernel<<<(unsigned)((nw / 4 + 255) / 256), 256>>>(w_qkv, whi, wlo, nw);
        const size_t np = (size_t)C_ * C_;
        split_w_kernel<<<(unsigned)((np / 4 + 255) / 256), 256>>>(w_proj, phi, plo, np);
    }

    // 1) QKV projection: (M x 768) @ (768 x 2304)^T + bias -> g_qkv (fp32)
    {
        dim3 grid(K3C / 128, M_ / 128);
        gemm_bf16x3_kernel<<<grid, 256, GEMM_SMEM>>>(xhi, xlo, whi, wlo,
                                                     b_qkv, qkv_buf, K3C, C_);
    }

    // 2) Attention -> bf16 split output
    attention_kernel<<<B_ * H_, 256>>>(qkv_buf, mask, ahi, alo);

    // 3) Output projection -> d_out
    {
        dim3 grid(C_ / 128, M_ / 128);
        gemm_bf16x3_kernel<<<grid, 256, GEMM_SMEM>>>(ahi, alo, phi, plo,
                                                     b_proj, out, C_, C_);
    }
}

// round 6
// speedup vs baseline: 2.7528x; 1.1283x over previous
#include <cuda_runtime.h>
#include <cuda_bf16.h>
#include <math_constants.h>
#include <cstdint>

// Problem constants
#define B_   1024
#define NTOK 68
#define C_   768
#define H_   12
#define HD   64
#define M_   (B_ * NTOK)        // 69632
#define K3C  (3 * C_)           // 2304

// Scratch (__device__ globals; allocation-free rule)
__device__ float         g_qkv[(size_t)M_ * K3C];   // QKV output fp32
__device__ __nv_bfloat16 g_xhi[(size_t)M_ * C_];    // x+pe split
__device__ __nv_bfloat16 g_xlo[(size_t)M_ * C_];
__device__ __nv_bfloat16 g_whi[(size_t)K3C * C_];   // w_qkv split
__device__ __nv_bfloat16 g_wlo[(size_t)K3C * C_];
__device__ __nv_bfloat16 g_phi[(size_t)C_ * C_];    // w_proj split
__device__ __nv_bfloat16 g_plo[(size_t)C_ * C_];
__device__ __nv_bfloat16 g_ahi[(size_t)M_ * C_];    // attention out split
__device__ __nv_bfloat16 g_alo[(size_t)M_ * C_];

// ---------------------------------------------------------------------------
// helpers
// ---------------------------------------------------------------------------
static __device__ __forceinline__ uint32_t smem_u32(const void* p) {
    uint32_t a;
    asm("{ .reg .u64 t; cvta.to.shared.u64 t, %1; cvt.u32.u64 %0, t; }"
        : "=r"(a) : "l"(p));
    return a;
}

static __device__ __forceinline__ void split2(float v, __nv_bfloat16& h,
                                              __nv_bfloat16& l) {
    h = __float2bfloat16_rn(v);
    l = __float2bfloat16_rn(v - __bfloat162float(h));
}

#define CP16(dst, src) \
    asm volatile("cp.async.cg.shared.global [%0], [%1], 16;" \
                 :: "r"(dst), "l"(src))
#define CP_COMMIT() asm volatile("cp.async.commit_group;" ::: "memory")
#define CP_WAIT2()  asm volatile("cp.async.wait_group 2;"  ::: "memory")

#define LDSM_X4(r, addr) \
    asm volatile("ldmatrix.sync.aligned.m8n8.x4.shared.b16 {%0,%1,%2,%3}, [%4];" \
                 : "=r"((r)[0]), "=r"((r)[1]), "=r"((r)[2]), "=r"((r)[3]) \
                 : "r"(addr))

#define MMA_BF16(d, a, b0, b1) \
    asm volatile("mma.sync.aligned.m16n8k16.row.col.f32.bf16.bf16.f32 " \
                 "{%0,%1,%2,%3}, {%4,%5,%6,%7}, {%8,%9}, {%0,%1,%2,%3};" \
                 : "+f"((d)[0]), "+f"((d)[1]), "+f"((d)[2]), "+f"((d)[3]) \
                 : "r"((a)[0]), "r"((a)[1]), "r"((a)[2]), "r"((a)[3]), \
                   "r"(b0), "r"(b1))

// smem tile: 128 rows x 64 bytes (32 bf16/row), XOR swizzle (conflict-free
// ldmatrix). 4 stages x 4 tiles (Ahi, Alo, Bhi, Blo) x 8KB = 128KB.
static __device__ __forceinline__ uint32_t sw_off(int row, int c) {
    const int s = (row & 3) ^ ((row >> 2) & 3);
    return (uint32_t)(row * 64 + ((c ^ s) << 4));
}
#define TILE_ST(s, w) ((s) * 32768 + (w) * 8192)
#define GEMM_SMEM 131072

// ---------------------------------------------------------------------------
// split kernels (fp32 -> bf16 hi/lo pair)
// ---------------------------------------------------------------------------
__global__ void split_x_pe_kernel(const float* __restrict__ x,
                                  const float* __restrict__ pe,
                                  __nv_bfloat16* __restrict__ hi,
                                  __nv_bfloat16* __restrict__ lo)
{
    const size_t i4 = (size_t)blockIdx.x * blockDim.x + threadIdx.x;
    const size_t e  = i4 * 4;
    if (e >= (size_t)M_ * C_) return;
    const int row = (int)(e / C_);
    const int col = (int)(e % C_);
    const int tok = row % NTOK;

    float4 v = *reinterpret_cast<const float4*>(x + e);
    if (tok >= 4) {
        const float4 p = *reinterpret_cast<const float4*>(
            pe + (size_t)(tok + 28) * C_ + col);
        v.x += p.x; v.y += p.y; v.z += p.z; v.w += p.w;
    }
    __nv_bfloat16 h0, l0, h1, l1, h2, l2, h3, l3;
    split2(v.x, h0, l0); split2(v.y, h1, l1);
    split2(v.z, h2, l2); split2(v.w, h3, l3);
    __nv_bfloat162* hp = reinterpret_cast<__nv_bfloat162*>(hi + e);
    __nv_bfloat162* lp = reinterpret_cast<__nv_bfloat162*>(lo + e);
    hp[0] = __nv_bfloat162(h0, h1); hp[1] = __nv_bfloat162(h2, h3);
    lp[0] = __nv_bfloat162(l0, l1); lp[1] = __nv_bfloat162(l2, l3);
}

__global__ void split_w_kernel(const float* __restrict__ w,
                               __nv_bfloat16* __restrict__ hi,
                               __nv_bfloat16* __restrict__ lo,
                               size_t n_elem)
{
    const size_t i4 = (size_t)blockIdx.x * blockDim.x + threadIdx.x;
    const size_t e  = i4 * 4;
    if (e >= n_elem) return;
    const float4 v = *reinterpret_cast<const float4*>(w + e);
    __nv_bfloat16 h0, l0, h1, l1, h2, l2, h3, l3;
    split2(v.x, h0, l0); split2(v.y, h1, l1);
    split2(v.z, h2, l2); split2(v.w, h3, l3);
    __nv_bfloat162* hp = reinterpret_cast<__nv_bfloat162*>(hi + e);
    __nv_bfloat162* lp = reinterpret_cast<__nv_bfloat162*>(lo + e);
    hp[0] = __nv_bfloat162(h0, h1); hp[1] = __nv_bfloat162(h2, h3);
    lp[0] = __nv_bfloat162(l0, l1); lp[1] = __nv_bfloat162(l2, l3);
}

// ---------------------------------------------------------------------------
// GEMM: C[m][n] = sum_k (Ahi+Alo)[m][k] * (Bhi+Blo)[n][k] + bias[n]
// D = Ahi*Bhi + Ahi*Blo + Alo*Bhi  (bf16 mma.sync, fp32 accum).
// CTA 128x128, 512 threads / 16 warps (2m x 8n), warp tile 64x16,
// K-chunk 32, 4-stage cp.async ring, term-major MMA schedule.
// ---------------------------------------------------------------------------
__global__ __launch_bounds__(512)
void gemm_bf16x3_kernel(const __nv_bfloat16* __restrict__ Ahi,
                        const __nv_bfloat16* __restrict__ Alo,
                        const __nv_bfloat16* __restrict__ Bhi,
                        const __nv_bfloat16* __restrict__ Blo,
                        const float* __restrict__ bias,
                        float* __restrict__ Cout,
                        int N, int K)
{
    extern __shared__ char smem[];
    const uint32_t sb = smem_u32(smem);

    const int tid  = threadIdx.x;
    const int wid  = tid >> 5;   // 0..15
    const int lane = tid & 31;
    const int cN   = blockIdx.x;
    const int cM   = blockIdx.y;
    const int wm   = wid & 1;    // 0..1
    const int wn   = wid >> 1;   // 0..7

    // ---- cp.async geometry: 1 x 16B per thread per tile (512 thr = full tile)
    const int r0 = tid >> 2, c0 = tid & 3;
    const uint32_t so0 = sw_off(r0, c0);
    const __nv_bfloat16* gAh = Ahi + (size_t)(cM * 128 + r0) * K + c0 * 8;
    const __nv_bfloat16* gAl = Alo + (size_t)(cM * 128 + r0) * K + c0 * 8;
    const __nv_bfloat16* gBh = Bhi + (size_t)(cN * 128 + r0) * K + c0 * 8;
    const __nv_bfloat16* gBl = Blo + (size_t)(cN * 128 + r0) * K + c0 * 8;

#define LOAD_STAGE(s, k0)                                 \
    do {                                                   \
        CP16(sb + TILE_ST(s, 0) + so0, gAh + (k0));        \
        CP16(sb + TILE_ST(s, 1) + so0, gAl + (k0));        \
        CP16(sb + TILE_ST(s, 2) + so0, gBh + (k0));        \
        CP16(sb + TILE_ST(s, 3) + so0, gBl + (k0));        \
    } while (0)

    // per-warp ldmatrix base offsets
    const int arow = wm * 64 + (lane & 15);   // + mf*16
    const int brow = wn * 16 + (lane & 15);
    const int chi  = lane >> 4;               // 16B column sub-chunk

    uint32_t Ah[4][4], Al[4][4], Bh[4], Bl[4];

#define FRAG_LOAD(st, t)                                                     \
    do {                                                                      \
        _Pragma("unroll")                                                     \
        for (int mf = 0; mf < 4; mf++) {                                      \
            const uint32_t ao = sw_off(arow + mf * 16, 2 * (t) + chi);        \
            LDSM_X4(Ah[mf], sb + TILE_ST(st, 0) + ao);                        \
            LDSM_X4(Al[mf], sb + TILE_ST(st, 1) + ao);                        \
        }                                                                     \
        const uint32_t bo = sw_off(brow, 2 * (t) + chi);                      \
        LDSM_X4(Bh, sb + TILE_ST(st, 2) + bo);                                \
        LDSM_X4(Bl, sb + TILE_ST(st, 3) + bo);                                \
    } while (0)

// term-major: 3 passes of 8 independent-accumulator MMAs each
#define MMA_ALL()                                                            \
    do {                                                                      \
        _Pragma("unroll")                                                     \
        for (int mf = 0; mf < 4; mf++) {                                      \
            _Pragma("unroll")                                                 \
            for (int nf = 0; nf < 2; nf++)                                    \
                MMA_BF16(acc[mf][nf], Ah[mf], Bh[nf], Bh[nf + 2]);            \
        }                                                                     \
        _Pragma("unroll")                                                     \
        for (int mf = 0; mf < 4; mf++) {                                      \
            _Pragma("unroll")                                                 \
            for (int nf = 0; nf < 2; nf++)                                    \
                MMA_BF16(acc[mf][nf], Ah[mf], Bl[nf], Bl[nf + 2]);            \
        }                                                                     \
        _Pragma("unroll")                                                     \
        for (int mf = 0; mf < 4; mf++) {                                      \
            _Pragma("unroll")                                                 \
            for (int nf = 0; nf < 2; nf++)                                    \
                MMA_BF16(acc[mf][nf], Al[mf], Bh[nf], Bh[nf + 2]);            \
        }                                                                     \
    } while (0)

    float acc[4][2][4];
#pragma unroll
    for (int i = 0; i < 4; i++)
#pragma unroll
        for (int j = 0; j < 2; j++)
#pragma unroll
            for (int r = 0; r < 4; r++) acc[i][j][r] = 0.0f;

    const int NC = K >> 5;   // 24

    // ---- prologue: 3 stages in flight ----
    LOAD_STAGE(0, 0);   CP_COMMIT();
    LOAD_STAGE(1, 32);  CP_COMMIT();
    LOAD_STAGE(2, 64);  CP_COMMIT();
    CP_WAIT2();
    __syncthreads();

    for (int kc = 0; kc < NC; kc++) {
        const int cur = kc & 3;

        FRAG_LOAD(cur, 0);
        MMA_ALL();

        FRAG_LOAD(cur, 1);
        if (kc + 3 < NC) LOAD_STAGE((kc + 3) & 3, (kc + 3) * 32);
        CP_COMMIT();
        MMA_ALL();

        if (kc + 1 < NC) {
            CP_WAIT2();
            __syncthreads();
        }
    }

    // ---- epilogue: bias + fp32 store ----
#pragma unroll
    for (int mf = 0; mf < 4; mf++) {
        const int row = cM * 128 + wm * 64 + mf * 16 + (lane >> 2);
#pragma unroll
        for (int nf = 0; nf < 2; nf++) {
            const int col = cN * 128 + wn * 16 + nf * 8 + (lane & 3) * 2;
            const float2 bb = *reinterpret_cast<const float2*>(bias + col);
            float2 o0, o1;
            o0.x = acc[mf][nf][0] + bb.x;  o0.y = acc[mf][nf][1] + bb.y;
            o1.x = acc[mf][nf][2] + bb.x;  o1.y = acc[mf][nf][3] + bb.y;
            *reinterpret_cast<float2*>(Cout + (size_t)row * N + col) = o0;
            *reinterpret_cast<float2*>(Cout + (size_t)(row + 8) * N + col) = o1;
        }
    }
#undef LOAD_STAGE
#undef FRAG_LOAD
#undef MMA_ALL
}

// ---------------------------------------------------------------------------
// Attention: one CTA per (b, h); 4 q-rows per warp per iteration so the
// sk/sv smem loads amortize 4x (crossbar-bound kernel).
// Writes bf16 hi/lo split of output directly.
// ---------------------------------------------------------------------------
__global__ __launch_bounds__(256)
void attention_kernel(const float* __restrict__ qkv,
                      const float* __restrict__ mask,
                      __nv_bfloat16* __restrict__ ohi,
                      __nv_bfloat16* __restrict__ olo)
{
    __shared__ float sk[NTOK][HD + 1];
    __shared__ float sv[NTOK][HD + 1];
    __shared__ float sq[8][4][HD];
    __shared__ float sp[8][4][NTOK];

    const int bh = blockIdx.x;
    const int b  = bh / H_;
    const int h  = bh % H_;
    const int tid  = threadIdx.x;
    const int warp = tid >> 5;
    const int lane = tid & 31;

    const size_t base = (size_t)b * NTOK * K3C + (size_t)h * HD;
    for (int idx = tid; idx < NTOK * HD; idx += 256) {
        const int j = idx / HD, d = idx % HD;
        sk[j][d] = qkv[base + (size_t)j * K3C + C_ + d];
        sv[j][d] = qkv[base + (size_t)j * K3C + 2 * C_ + d];
    }
    __syncthreads();

    const float scale = 0.125f;
    const float* mrow_base = mask + (size_t)b * NTOK * NTOK;
    const int j0 = lane;
    const int j1 = lane + 32;
    const int j2 = (lane < 4) ? lane + 64 : 67;   // clamped; masked below

    // 17 groups of 4 rows
    for (int g = warp; g < 17; g += 8) {
        const int row0 = g * 4;

        // stage 4 scaled q rows
#pragma unroll
        for (int r = 0; r < 4; r++) {
            sq[warp][r][lane]      = qkv[base + (size_t)(row0 + r) * K3C + lane]      * scale;
            sq[warp][r][lane + 32] = qkv[base + (size_t)(row0 + r) * K3C + lane + 32] * scale;
        }
        __syncwarp();

        // scores: 4 rows x 3 key slots; sk loads shared across the 4 rows
        float s[4][3];
#pragma unroll
        for (int r = 0; r < 4; r++)
            s[r][0] = s[r][1] = s[r][2] = 0.0f;

#pragma unroll
        for (int d = 0; d < HD; d++) {
            const float k0 = sk[j0][d];
            const float k1 = sk[j1][d];
            const float k2 = sk[j2][d];
#pragma unroll
            for (int r = 0; r < 4; r++) {
                const float q = sq[warp][r][d];
                s[r][0] = fmaf(q, k0, s[r][0]);
                s[r][1] = fmaf(q, k1, s[r][1]);
                s[r][2] = fmaf(q, k2, s[r][2]);
            }
        }

        // add mask; invalidate clamped j2 lanes
#pragma unroll
        for (int r = 0; r < 4; r++) {
            const float* mrow = mrow_base + (size_t)(row0 + r) * NTOK;
            s[r][0] += mrow[j0];
            s[r][1] += mrow[j1];
            s[r][2] = (lane < 4) ? (s[r][2] + mrow[j2]) : -CUDART_INF_F;
        }

        // softmax per row
#pragma unroll
        for (int r = 0; r < 4; r++) {
            float mx = fmaxf(fmaxf(s[r][0], s[r][1]), s[r][2]);
#pragma unroll
            for (int off = 16; off > 0; off >>= 1)
                mx = fmaxf(mx, __shfl_xor_sync(0xffffffffu, mx, off));

            const float e0 = __expf(s[r][0] - mx);
            const float e1 = __expf(s[r][1] - mx);
            const float e2 = (lane < 4) ? __expf(s[r][2] - mx) : 0.0f;
            float sum = e0 + e1 + e2;
#pragma unroll
            for (int off = 16; off > 0; off >>= 1)
                sum += __shfl_xor_sync(0xffffffffu, sum, off);
            const float inv = 1.0f / sum;

            sp[warp][r][j0] = e0 * inv;
            sp[warp][r][j1] = e1 * inv;
            if (lane < 4) sp[warp][r][j2] = e2 * inv;
        }
        __syncwarp();

        // PV: sv loads shared across the 4 rows
        float o[4][2];
#pragma unroll
        for (int r = 0; r < 4; r++) o[r][0] = o[r][1] = 0.0f;

#pragma unroll
        for (int j = 0; j < NTOK; j++) {
            const float v0 = sv[j][lane];
            const float v1 = sv[j][lane + 32];
#pragma unroll
            for (int r = 0; r < 4; r++) {
                const float p = sp[warp][r][j];
                o[r][0] = fmaf(p, v0, o[r][0]);
                o[r][1] = fmaf(p, v1, o[r][1]);
            }
        }

#pragma unroll
        for (int r = 0; r < 4; r++) {
            const size_t obase = ((size_t)b * NTOK + row0 + r) * C_ + (size_t)h * HD;
            __nv_bfloat16 hh, ll;
            split2(o[r][0], hh, ll);
            ohi[obase + lane]      = hh;  olo[obase + lane]      = ll;
            split2(o[r][1], hh, ll);
            ohi[obase + lane + 32] = hh;  olo[obase + lane + 32] = ll;
        }
        __syncwarp();
    }
}

// ---------------------------------------------------------------------------
extern "C" void kernel_launch(void* const* d_in, const int* in_sizes, int n_in,
                              void* d_out, int out_size)
{
    const float* x      = (const float*)d_in[0];
    const float* pe     = (const float*)d_in[1];
    const float* mask   = (const float*)d_in[2];
    const float* w_qkv  = (const float*)d_in[3];
    const float* b_qkv  = (const float*)d_in[4];
    const float* w_proj = (const float*)d_in[5];
    const float* b_proj = (const float*)d_in[6];
    float* out = (float*)d_out;

    float*         qkv_buf; cudaGetSymbolAddress((void**)&qkv_buf, g_qkv);
    __nv_bfloat16 *xhi, *xlo, *whi, *wlo, *phi, *plo, *ahi, *alo;
    cudaGetSymbolAddress((void**)&xhi, g_xhi);
    cudaGetSymbolAddress((void**)&xlo, g_xlo);
    cudaGetSymbolAddress((void**)&whi, g_whi);
    cudaGetSymbolAddress((void**)&wlo, g_wlo);
    cudaGetSymbolAddress((void**)&phi, g_phi);
    cudaGetSymbolAddress((void**)&plo, g_plo);
    cudaGetSymbolAddress((void**)&ahi, g_ahi);
    cudaGetSymbolAddress((void**)&alo, g_alo);

    cudaFuncSetAttribute(gemm_bf16x3_kernel,
                         cudaFuncAttributeMaxDynamicSharedMemorySize, GEMM_SMEM);

    // 0) precompute bf16 splits
    {
        const size_t nx = (size_t)M_ * C_ / 4;
        split_x_pe_kernel<<<(unsigned)((nx + 255) / 256), 256>>>(x, pe, xhi, xlo);
        const size_t nw = (size_t)K3C * C_;
        split_w_kernel<<<(unsigned)((nw / 4 + 255) / 256), 256>>>(w_qkv, whi, wlo, nw);
        const size_t np = (size_t)C_ * C_;
        split_w_kernel<<<(unsigned)((np / 4 + 255) / 256), 256>>>(w_proj, phi, plo, np);
    }

    // 1) QKV projection: (M x 768) @ (768 x 2304)^T + bias -> g_qkv (fp32)
    {
        dim3 grid(K3C / 128, M_ / 128);
        gemm_bf16x3_kernel<<<grid, 512, GEMM_SMEM>>>(xhi, xlo, whi, wlo,
                                                     b_qkv, qkv_buf, K3C, C_);
    }

    // 2) Attention -> bf16 split output
    attention_kernel<<<B_ * H_, 256>>>(qkv_buf, mask, ahi, alo);

    // 3) Output projection -> d_out
    {
        dim3 grid(C_ / 128, M_ / 128);
        gemm_bf16x3_kernel<<<grid, 512, GEMM_SMEM>>>(ahi, alo, phi, plo,
                                                     b_proj, out, C_, C_);
    }
}